// round 5
// baseline (speedup 1.0000x reference)
#include <cuda_runtime.h>
#include <cuda_fp16.h>

#define NUM_USERS 100000
#define NUM_ITEMS 50000
#define N_NODES   150000
#define DIM       64
#define N_EDGES   4800000

#define U_ELEMS (NUM_USERS * DIM)   // 6,400,000
#define I_ELEMS (NUM_ITEMS * DIM)   // 3,200,000

#define SCAN_TILE 1024
#define SCAN_NBLK ((N_NODES + SCAN_TILE - 1) / SCAN_TILE)   // 147

// ---------------- static device scratch (no dynamic allocation allowed) ----
// Node features fp16: row = 32 half2 = 128 bytes.
__device__ __half2 g_x0h[(size_t)N_NODES * 32];   // emb0   (fp16)
__device__ __half2 g_h1h[(size_t)N_NODES * 32];   // hop 1  (fp16)
__device__ __half2 g_h2h[(size_t)N_NODES * 32];   // hop 2  (fp16)
__device__ int   g_rowptr[N_NODES + 1];
__device__ int   g_cnt [N_NODES];
__device__ int   g_fill[N_NODES];
__device__ int   g_part[SCAN_NBLK];
__device__ int2  g_cw  [N_EDGES];                 // interleaved {col, w_bits(fp32)}
__device__ int   g_is64;

// ---------------- detect dtype (int64 vs int32) + zero counters ------------
__global__ void k_detect_zero(const int* __restrict__ ei32) {
    int i = blockIdx.x * blockDim.x + threadIdx.x;
    if (i < N_NODES) g_cnt[i] = 0;
    if (blockIdx.x == 0 && threadIdx.x < 32) {
        int v = ei32[2 * threadIdx.x + 1];
        unsigned b = __ballot_sync(0xffffffffu, v == 0);
        if (threadIdx.x == 0) g_is64 = (b == 0xffffffffu) ? 1 : 0;
    }
}

__device__ __forceinline__ int load_edge_idx(const void* ei, long long i, int is64) {
    if (is64) return (int)((const long long*)ei)[i];
    return ((const int*)ei)[i];
}

// ---------------- init (emb0 -> fp16, echo -> out) + row histogram ---------
// Thread e: converts concat elements [2e, 2e+1] AND counts edge e.
// out layout: [u_final | users_emb | i_final | items_emb]
__global__ void k_init_count(const float* __restrict__ users,
                             const float* __restrict__ items,
                             const void*  __restrict__ ei,
                             float* __restrict__ out) {
    int is64 = g_is64;
    int e = blockIdx.x * blockDim.x + threadIdx.x;
    if (e >= N_EDGES) return;   // N_EDGES = N_NODES*DIM/2, same grid covers both

    int j = 2 * e;
    float2 v;
    if (j < U_ELEMS) {
        v = *(const float2*)(users + j);
        *(float2*)(out + U_ELEMS + j) = v;                        // users echo
    } else {
        int jj = j - U_ELEMS;
        v = *(const float2*)(items + jj);
        *(float2*)(out + 2 * U_ELEMS + I_ELEMS + jj) = v;         // items echo
    }
    g_x0h[e] = __float22half2_rn(v);

    int r = load_edge_idx(ei, e, is64);
    atomicAdd(&g_cnt[r], 1);
}

// ---------------- scan phase 1: per-1024-tile partial sums -----------------
__global__ void k_partials() {
    __shared__ int sh[256];
    int b = blockIdx.x, t = threadIdx.x;
    int base = b * SCAN_TILE + t * 4;
    int s = 0;
    #pragma unroll
    for (int k = 0; k < 4; ++k) {
        int i = base + k;
        if (i < N_NODES) s += g_cnt[i];
    }
    sh[t] = s;
    __syncthreads();
    for (int off = 128; off > 0; off >>= 1) {
        if (t < off) sh[t] += sh[t + off];
        __syncthreads();
    }
    if (t == 0) g_part[b] = sh[0];
}

// ---------------- scan phase 2: per-block writeptr with inline partial scan
__global__ void k_writeptr() {
    __shared__ int shp[256];
    __shared__ int sh[256];
    int b = blockIdx.x, t = threadIdx.x;

    int pv = (t < SCAN_NBLK) ? g_part[t] : 0;
    shp[t] = pv;
    __syncthreads();
    for (int off = 1; off < 256; off <<= 1) {
        int x = (t >= off) ? shp[t - off] : 0;
        __syncthreads();
        shp[t] += x;
        __syncthreads();
    }
    if (b == 0 && t == SCAN_NBLK - 1) g_rowptr[N_NODES] = shp[t];
    int blockOff = (b == 0) ? 0 : shp[b - 1];

    int base = b * SCAN_TILE + t * 4;
    int c0 = 0, c1 = 0, c2 = 0, c3 = 0;
    if (base + 0 < N_NODES) c0 = g_cnt[base + 0];
    if (base + 1 < N_NODES) c1 = g_cnt[base + 1];
    if (base + 2 < N_NODES) c2 = g_cnt[base + 2];
    if (base + 3 < N_NODES) c3 = g_cnt[base + 3];
    int s = c0 + c1 + c2 + c3;
    sh[t] = s;
    __syncthreads();
    for (int off = 1; off < 256; off <<= 1) {
        int x = (t >= off) ? sh[t - off] : 0;
        __syncthreads();
        sh[t] += x;
        __syncthreads();
    }
    int run = blockOff + (sh[t] - s);
    if (base + 0 < N_NODES) { g_rowptr[base + 0] = run; g_fill[base + 0] = run; run += c0; }
    if (base + 1 < N_NODES) { g_rowptr[base + 1] = run; g_fill[base + 1] = run; run += c1; }
    if (base + 2 < N_NODES) { g_rowptr[base + 2] = run; g_fill[base + 2] = run; run += c2; }
    if (base + 3 < N_NODES) { g_rowptr[base + 3] = run; g_fill[base + 3] = run; run += c3; }
}

// ---------------- scatter edges into CSR: 4 edges/thread (MLP=4) -----------
__global__ void k_scatter(const void* __restrict__ ei,
                          const float* __restrict__ ew) {
    int is64 = g_is64;
    int e0 = (blockIdx.x * blockDim.x + threadIdx.x) * 4;
    if (e0 >= N_EDGES) return;
    int r[4], c[4]; float w[4];
    #pragma unroll
    for (int k = 0; k < 4; ++k) {
        int e = e0 + k;           // N_EDGES % 4 == 0, always in range
        r[k] = load_edge_idx(ei, e, is64);
        c[k] = load_edge_idx(ei, (long long)N_EDGES + e, is64);
        w[k] = ew[e];
    }
    int pos[4];
    #pragma unroll
    for (int k = 0; k < 4; ++k) pos[k] = atomicAdd(&g_fill[r[k]], 1);
    #pragma unroll
    for (int k = 0; k < 4; ++k) g_cw[pos[k]] = make_int2(c[k], __float_as_int(w[k]));
}

// ---------------- SpMM: half-warp per row ----------------------------------
// Warp handles rows 2*warp (lanes 0-15) and 2*warp+1 (lanes 16-31).
// Lane owns 4 dims: loads one int2 (= 2 half2 = 8 B) per edge, 16 lanes cover
// the 128-B row. Edge (c,w) staged 16-at-a-time per half, broadcast with
// width-16 shfl (one instruction serves both halves). Accumulate fp32.
__device__ __forceinline__ void spmm_row_hw(const __half2* __restrict__ src,
                                            int row, int hl,
                                            float& a0, float& a1,
                                            float& a2, float& a3) {
    int start = g_rowptr[row];
    int end   = g_rowptr[row + 1];
    a0 = a1 = a2 = a3 = 0.f;
    for (int base = start; base < end; base += 16) {
        int j = base + hl;
        int2 cw = make_int2(0, 0);
        if (j < end) cw = __ldg(&g_cw[j]);
        int m = end - base; if (m > 16) m = 16;
        #pragma unroll 8
        for (int k = 0; k < m; ++k) {
            int   cc = __shfl_sync(0xffffffffu, cw.x, k, 16);
            float wk = __int_as_float(__shfl_sync(0xffffffffu, cw.y, k, 16));
            int2 hv = __ldg((const int2*)(src + ((size_t)cc << 5) + 2 * hl));
            float2 v0 = __half22float2(*(const __half2*)&hv.x);
            float2 v1 = __half22float2(*(const __half2*)&hv.y);
            a0 = fmaf(wk, v0.x, a0);
            a1 = fmaf(wk, v0.y, a1);
            a2 = fmaf(wk, v1.x, a2);
            a3 = fmaf(wk, v1.y, a3);
        }
    }
}

// hops 1 and 2: sel==0: x0 -> h1 ; sel==1: h1 -> h2
__global__ void __launch_bounds__(256) k_spmm(int sel) {
    const __half2* __restrict__ src = sel ? g_h1h : g_x0h;
    __half2*       __restrict__ dst = sel ? g_h2h : g_h1h;
    int warp = (blockIdx.x * blockDim.x + threadIdx.x) >> 5;
    int lane = threadIdx.x & 31;
    int hl   = lane & 15;
    int row  = 2 * warp + (lane >> 4);
    if (row >= N_NODES) return;
    float a0, a1, a2, a3;
    spmm_row_hw(src, row, hl, a0, a1, a2, a3);
    int2 hv;
    *(__half2*)&hv.x = __float22half2_rn(make_float2(a0, a1));
    *(__half2*)&hv.y = __float22half2_rn(make_float2(a2, a3));
    *(int2*)(dst + ((size_t)row << 5) + 2 * hl) = hv;
}

// hop 3 fused with finalization: out_row = (emb0 + h1 + h2 + h3) * 0.25
__global__ void __launch_bounds__(256) k_spmm_last(const float* __restrict__ users,
                                                   const float* __restrict__ items,
                                                   float* __restrict__ out) {
    int warp = (blockIdx.x * blockDim.x + threadIdx.x) >> 5;
    int lane = threadIdx.x & 31;
    int hl   = lane & 15;
    int row  = 2 * warp + (lane >> 4);
    if (row >= N_NODES) return;
    float a0, a1, a2, a3;
    spmm_row_hw(g_h2h, row, hl, a0, a1, a2, a3);    // h3 partial (fp32)

    size_t ro = ((size_t)row << 6) + 4 * hl;        // float index (16B aligned)
    size_t rh = ((size_t)row << 5) + 2 * hl;        // half2 index
    const float* e0p = (row < NUM_USERS)
                     ? (users + ro)
                     : (items + ro - (size_t)U_ELEMS);
    float4 e0 = *(const float4*)e0p;                // exact fp32 emb0
    int2 h1v = *(const int2*)(g_h1h + rh);
    int2 h2v = *(const int2*)(g_h2h + rh);
    float2 h10 = __half22float2(*(const __half2*)&h1v.x);
    float2 h11 = __half22float2(*(const __half2*)&h1v.y);
    float2 h20 = __half22float2(*(const __half2*)&h2v.x);
    float2 h21 = __half22float2(*(const __half2*)&h2v.y);

    float4 o;
    o.x = (e0.x + h10.x + h20.x + a0) * 0.25f;
    o.y = (e0.y + h10.y + h20.y + a1) * 0.25f;
    o.z = (e0.z + h11.x + h21.x + a2) * 0.25f;
    o.w = (e0.w + h11.y + h21.y + a3) * 0.25f;

    float* op = (row < NUM_USERS)
              ? (out + ro)                                     // u_final
              : (out + 2 * (size_t)U_ELEMS + (ro - U_ELEMS));  // i_final
    *(float4*)op = o;
}

// ---------------- launch ----------------------------------------------------
extern "C" void kernel_launch(void* const* d_in, const int* in_sizes, int n_in,
                              void* d_out, int out_size) {
    const float* users = (const float*)d_in[0];
    const float* items = (const float*)d_in[1];
    const void*  ei    = d_in[2];   // int64 or int32, detected on device
    const float* ew    = (const float*)d_in[3];
    float* out = (float*)d_out;

    k_detect_zero<<<(N_NODES + 255) / 256, 256>>>((const int*)ei);

    k_init_count<<<(N_EDGES + 255) / 256, 256>>>(users, items, ei, out);

    k_partials<<<SCAN_NBLK, 256>>>();
    k_writeptr<<<SCAN_NBLK, 256>>>();

    k_scatter<<<(N_EDGES / 4 + 255) / 256, 256>>>(ei, ew);

    {
        int warps = (N_NODES + 1) / 2;               // 2 rows per warp
        int threads = warps * 32;
        int blocks = (threads + 255) / 256;
        k_spmm<<<blocks, 256>>>(0);                       // x0 -> h1
        k_spmm<<<blocks, 256>>>(1);                       // h1 -> h2
        k_spmm_last<<<blocks, 256>>>(users, items, out);  // h2 -> out (fused)
    }
}